// round 14
// baseline (speedup 1.0000x reference)
#include <cuda_runtime.h>
#include <cuda_fp16.h>
#include <cstdint>
#include <math.h>

// Problem constants
#define NB 8
#define LL 12
#define NN 1024
#define HH 32
#define H2 64
#define AF 48
#define NDIM 16

// Scratch (device globals)
__device__ float d_h[8192 * H2];
__device__ float d_part[64][H2][2];
__device__ float d_Q[2 * 8192 * HH];
__device__ float d_K[2 * 8192 * HH];
__device__ __half d_gh[16ull * 1024 * 1024];   // 32 MB fp16 graphs

extern __shared__ char dynsmem[];

// ---------------------------------------------------------------------------
#define SWZ128(o) ((o) ^ (((o) >> 3) & 0x70))
#define CP_ASYNC16(dst, src) asm volatile("cp.async.cg.shared.global [%0], [%1], 16;" :: "r"(dst), "l"(src))
#define CP_ASYNC4(dst, src)  asm volatile("cp.async.ca.shared.global [%0], [%1], 4;"  :: "r"(dst), "l"(src))
#define CP_COMMIT() asm volatile("cp.async.commit_group;" ::: "memory")
#define CP_WAIT1() asm volatile("cp.async.wait_group 1;" ::: "memory")
#define CP_WAIT0() asm volatile("cp.async.wait_group 0;" ::: "memory")
#define LDSM4(r0, r1, r2, r3, addr) \
    asm volatile("ldmatrix.sync.aligned.m8n8.x4.shared.b16 {%0,%1,%2,%3}, [%4];" \
        : "=r"(r0), "=r"(r1), "=r"(r2), "=r"(r3) : "r"(addr))
#define LDSM4T(r0, r1, r2, r3, addr) \
    asm volatile("ldmatrix.sync.aligned.m8n8.x4.trans.shared.b16 {%0,%1,%2,%3}, [%4];" \
        : "=r"(r0), "=r"(r1), "=r"(r2), "=r"(r3) : "r"(addr))

__device__ __forceinline__ uint32_t smem_u32(const void* p) {
    uint32_t a;
    asm("{ .reg .u64 t; cvta.to.shared.u64 t, %1; cvt.u32.u64 %0, t; }" : "=r"(a) : "l"(p));
    return a;
}
__device__ __forceinline__ float ex2(float x) {
    float y;
    asm("ex2.approx.ftz.f32 %0, %1;" : "=f"(y) : "f"(x));
    return y;
}
__device__ __forceinline__ void mma_fp16(float* c, const uint32_t* a, const uint32_t* b) {
    asm volatile(
        "mma.sync.aligned.m16n8k16.row.col.f32.f16.f16.f32 "
        "{%0,%1,%2,%3}, {%4,%5,%6,%7}, {%8,%9}, {%0,%1,%2,%3};"
        : "+f"(c[0]), "+f"(c[1]), "+f"(c[2]), "+f"(c[3])
        : "r"(a[0]), "r"(a[1]), "r"(a[2]), "r"(a[3]), "r"(b[0]), "r"(b[1]));
}

// ---------------------------------------------------------------------------
// Kernel 1: h = relu(X @ W1 + b1)
__global__ void k_h(const float* __restrict__ hd, const float* __restrict__ W1,
                    const float* __restrict__ b1, float* __restrict__ h) {
    __shared__ float sW[LL * H2];
    __shared__ float sb[H2];
    int tid = threadIdx.x;
    for (int i = tid; i < LL * H2; i += 256) sW[i] = W1[i];
    if (tid < H2) sb[tid] = b1[tid];
    __syncthreads();
    int row = blockIdx.x * 4 + (tid >> 6);
    int col = tid & 63;
    int b = row >> 10, n = row & 1023;
    float acc = sb[col];
#pragma unroll
    for (int l = 0; l < LL; l++)
        acc += hd[((size_t)(b * LL + l) << 10) + n] * sW[l * H2 + col];
    h[(size_t)row * H2 + col] = fmaxf(acc, 0.f);
}

// ---------------------------------------------------------------------------
// Kernel 2: coalesced partial BN sums. 64 blocks x 128 rows each.
__global__ void k_stats1(const float* __restrict__ h, float* __restrict__ part) {
    __shared__ float ps[4][H2], ps2[4][H2];
    int tid = threadIdx.x;
    int c = tid & 63, r0 = tid >> 6;
    int p = blockIdx.x;
    float s = 0.f, s2 = 0.f;
#pragma unroll
    for (int i = 0; i < 32; i++) {
        float v = h[(size_t)(p * 128 + i * 4 + r0) * H2 + c];
        s += v; s2 += v * v;
    }
    ps[r0][c] = s; ps2[r0][c] = s2;
    __syncthreads();
    if (tid < H2) {
        float a = 0.f, b = 0.f;
#pragma unroll
        for (int j = 0; j < 4; j++) { a += ps[j][tid]; b += ps2[j][tid]; }
        part[(p * H2 + tid) * 2 + 0] = a;
        part[(p * H2 + tid) * 2 + 1] = b;
    }
}

// ---------------------------------------------------------------------------
// Kernel 3: fused BN-finalize + dy + Q/K projections.
// 16 rows per 256-thread block, 512 blocks (~3.5 resident/SM).
__global__ void __launch_bounds__(256)
k_dyqk(const float* __restrict__ h, const float* __restrict__ part,
       const float* __restrict__ gamma, const float* __restrict__ beta,
       const float* __restrict__ W2, const float* __restrict__ b2,
       const float* __restrict__ embd, const float* __restrict__ embu,
       const float* __restrict__ WQ, const float* __restrict__ WK,
       float* __restrict__ Q, float* __restrict__ K) {
    __shared__ float sW2[H2 * HH];
    __shared__ float sWQ[AF * HH];
    __shared__ float sWK[AF * HH];
    __shared__ float sb2[HH];
    __shared__ float ssc[H2], ssh[H2];
    __shared__ float shh[16][H2];
    __shared__ float sed[16][NDIM], seu[16][NDIM];
    __shared__ float sdy[16][HH];
    int tid = threadIdx.x;
    int row0 = blockIdx.x * 16;
    int n0 = row0 & 1023;

    // BN finalize (redundant per block; hidden behind weight staging)
    if (tid < H2) {
        float s = 0.f, s2 = 0.f;
#pragma unroll 8
        for (int p = 0; p < 64; p++) {
            s  += part[(p * H2 + tid) * 2 + 0];
            s2 += part[(p * H2 + tid) * 2 + 1];
        }
        float mu = s * (1.f / 8192.f);
        float var = s2 * (1.f / 8192.f) - mu * mu;
        float sc = gamma[tid] * rsqrtf(var + 1e-5f);
        ssc[tid] = sc;
        ssh[tid] = beta[tid] - mu * sc;
    }
    for (int i = tid; i < H2 * HH; i += 256) sW2[i] = W2[i];
    for (int i = tid; i < AF * HH; i += 256) { sWQ[i] = WQ[i]; sWK[i] = WK[i]; }
    if (tid < HH) sb2[tid] = b2[tid];
    if (tid < 16 * NDIM) {
        int r = tid >> 4, k = tid & 15;
        sed[r][k] = embd[(n0 + r) * NDIM + k];
        seu[r][k] = embu[(n0 + r) * NDIM + k];
    }
    __syncthreads();
    for (int i = tid; i < 16 * H2; i += 256) {
        int r = i >> 6, c = i & 63;
        shh[r][c] = h[(size_t)(row0 + r) * H2 + c] * ssc[c] + ssh[c];
    }
    __syncthreads();

    int rr = tid >> 5, c = tid & 31;
#pragma unroll
    for (int p = 0; p < 2; p++) {
        int r = p * 8 + rr;
        float acc = sb2[c];
#pragma unroll
        for (int k = 0; k < H2; k++) acc += shh[r][k] * sW2[k * HH + c];
        sdy[r][c] = acc;
    }
    __syncthreads();

#pragma unroll
    for (int p = 0; p < 2; p++) {
        int r = p * 8 + rr;
        float q0 = 0.f, k0 = 0.f;
#pragma unroll
        for (int k = 0; k < HH; k++) {
            float f = sdy[r][k];
            q0 += f * sWQ[k * HH + c];
            k0 += f * sWK[k * HH + c];
        }
        float qd = q0, qu = q0, kd = k0, ku = k0;
#pragma unroll
        for (int k = 0; k < NDIM; k++) {
            float wq = sWQ[(HH + k) * HH + c];
            float wk = sWK[(HH + k) * HH + c];
            qd += sed[r][k] * wq; qu += seu[r][k] * wq;
            kd += sed[r][k] * wk; ku += seu[r][k] * wk;
        }
        size_t od = (size_t)(row0 + r) * HH + c;
        size_t ou = (size_t)(8192 + row0 + r) * HH + c;
        Q[od] = qd; Q[ou] = qu;
        K[od] = kd; K[ou] = ku;
    }
}

// ---------------------------------------------------------------------------
// Kernel 4: attention. 16 rows / 512 threads per CTA; K staged via cp.async
// double buffering. exp+mask+partial-sums fused into phase 1; phase 2 is pure
// rescale+write. smem: sQ 2K + sK 2x18K + sV 64K + sRed 256B ~= 104.7KB.
#define SK_P 36
#define SK_FLOATS (128 * SK_P)
#define PSC 0.25507600725815733f   // (1/sqrt(32)) * log2(e)
__global__ void __launch_bounds__(512, 2)
k_attn(const float* __restrict__ Q, const float* __restrict__ K,
       const float* __restrict__ adj0, const float* __restrict__ adj1,
       __half* __restrict__ gh, float* __restrict__ out) {
    float* smemf = (float*)dynsmem;
    float* sQ = smemf;                            // 512
    float* sK0 = smemf + 512;                     // 128*36
    float* sK1 = sK0 + SK_FLOATS;
    float* sV = sK1 + SK_FLOATS;                  // 16*1024
    float* sRed = sV + 16 * 1024;                 // 16 rows x 4 warps
    uint32_t sk0a = smem_u32(sK0), sk1a = smem_u32(sK1);
    int tid = threadIdx.x;
    int blk = blockIdx.x;
    int e = blk >> 9;
    int rb = blk & 511;
    int b = rb >> 6;
    int row0 = (rb & 63) * 16;
    const float* adj = e ? adj1 : adj0;
    size_t qbase = ((size_t)e * 8192 + b * 1024 + row0) * HH;
    size_t kbase = ((size_t)e * 8192 + b * 1024) * HH;
    sQ[tid] = Q[qbase + tid];
    int tg = tid >> 7;        // 0..3 -> rows tg*4..tg*4+3
    int tl = tid & 127;       // column within chunk
    int r0 = tg * 4;
    int w = tid >> 5, lane = tid & 31;
    int wi = w & 3;           // warp index within row-group

    // prologue: stage chunk 0 into buf0
    {
#pragma unroll
        for (int p = 0; p < 8; p++) {
            int i = tid + p * 512;
            int m = i >> 5, k = i & 31;
            CP_ASYNC4(sk0a + (uint32_t)(m * SK_P + k) * 4, &K[kbase + i]);
        }
        CP_COMMIT();
    }

    float psum[4] = {0.f, 0.f, 0.f, 0.f};

    for (int t = 0; t < 8; t++) {
        __syncthreads();
        if (t < 7) {
            uint32_t dst = ((t + 1) & 1) ? sk1a : sk0a;
#pragma unroll
            for (int p = 0; p < 8; p++) {
                int i = tid + p * 512;
                int m = i >> 5, k = i & 31;
                CP_ASYNC4(dst + (uint32_t)(m * SK_P + k) * 4, &K[kbase + (t + 1) * 4096 + i]);
            }
            CP_COMMIT();
            CP_WAIT1();
        } else {
            CP_WAIT0();
        }
        __syncthreads();
        float* sK = (t & 1) ? sK1 : sK0;
        float4 kreg[8];
#pragma unroll
        for (int k4 = 0; k4 < 8; k4++)
            kreg[k4] = *(const float4*)&sK[tl * SK_P + k4 * 4];
        int m = t * 128 + tl;
#pragma unroll
        for (int r = 0; r < 4; r++) {
            float acc = 0.f;
#pragma unroll
            for (int q4 = 0; q4 < 8; q4++) {
                float4 qv = *(const float4*)&sQ[(r0 + r) * 32 + q4 * 4];
                acc += qv.x * kreg[q4].x;
                acc += qv.y * kreg[q4].y;
                acc += qv.z * kreg[q4].z;
                acc += qv.w * kreg[q4].w;
            }
            float e2 = ex2(acc * PSC);
            float a = adj[(size_t)(row0 + r0 + r) * 1024 + m];
            float vv = e2 * a + e2 * 1e-7f;
            sV[(r0 + r) * 1024 + m] = vv;
            psum[r] += vv;
        }
    }
    // reduce partial sums: warp shuffle, then one entry per (row, warp-in-group)
#pragma unroll
    for (int r = 0; r < 4; r++) {
        float s = psum[r];
        for (int o = 16; o > 0; o >>= 1) s += __shfl_xor_sync(0xffffffffu, s, o);
        if (lane == 0) sRed[(r0 + r) * 4 + wi] = s;
    }
    __syncthreads();

    // phase 2: per-warp row, pure rescale + write
    int n = row0 + w;
    float sum = sRed[w * 4 + 0] + sRed[w * 4 + 1] + sRed[w * 4 + 2] + sRed[w * 4 + 3];
    float inv = 1.f / sum;
    if (!isfinite(inv)) inv = 0.f;

    size_t gbase = ((size_t)e * 8192 + b * 1024 + n) * 1024;
    size_t obase = (size_t)(2 * e) * (16ull << 20) + ((size_t)b * 1024 + n) * 2048;
#pragma unroll
    for (int i = 0; i < 8; i++) {
        int m0 = i * 128 + lane * 4;
        float4 val = *(const float4*)&sV[w * 1024 + m0];
        val.x *= inv; val.y *= inv; val.z *= inv; val.w *= inv;
        __half2 lo = __floats2half2_rn(val.x, val.y);
        __half2 hi = __floats2half2_rn(val.z, val.w);
        uint2 gv = make_uint2(*(uint32_t*)&lo, *(uint32_t*)&hi);
        *(uint2*)&gh[gbase + m0] = gv;
        int d = n - m0;
        if (d >= 0 && d < 4) ((float*)&val)[d] = 0.f;
        *(float4*)&out[obase + m0] = val;
        *(float4*)&out[obase + 1024 + m0] = val;
    }
}

// ---------------------------------------------------------------------------
// Kernel 5: fp16 mma.sync GEMM, persistent CTAs. Block tile 128x128, 128 thr,
// warp tile 64x64, k-chunk 64, cp.async double buffering, 2 CTAs/SM, grid=296.
#define A_BYTES 16384
#define B_PITCH 272
#define B_BYTES (64 * B_PITCH)
#define GEMM_SMEM (2 * A_BYTES + 2 * B_BYTES)
#define N_TILES 1024

__global__ void __launch_bounds__(128, 2)
k_gemm_fp16(const __half* __restrict__ gh, float* __restrict__ out) {
    char* smem = dynsmem;
    uint32_t sb = smem_u32(smem);
    const uint32_t AOFF[2] = {0u, A_BYTES};
    const uint32_t BOFF[2] = {2 * A_BYTES, 2 * A_BYTES + B_BYTES};
    int tid = threadIdx.x;

    int wid = tid >> 5, lane = tid & 31;
    int gid = lane >> 2, tig = lane & 3;
    int warp_m = wid & 1, warp_n = wid >> 1;
    int rb0 = warp_m * 64, cb0 = warp_n * 64;
    int lr = lane & 7;
    int lm = (lane >> 3) & 1;
    int lk = lane >> 4;

    for (int tile = blockIdx.x; tile < N_TILES; tile += gridDim.x) {
        int eb = tile >> 6;
        int t6 = tile & 63;
        int tm = (t6 >> 3) * 128, tn = (t6 & 7) * 128;
        size_t base = (size_t)eb << 20;

        float acc[4][8][4];
#pragma unroll
        for (int i = 0; i < 4; i++)
#pragma unroll
            for (int j = 0; j < 8; j++)
#pragma unroll
                for (int q = 0; q < 4; q++) acc[i][j][q] = 0.f;

        auto load_chunk = [&](int c, int buf) {
            int k0 = c * 64;
#pragma unroll
            for (int q = 0; q < 8; q++) {
                int idx = tid + q * 128;
                int r = idx >> 3, s = idx & 7;
                uint32_t dst = sb + AOFF[buf] + SWZ128((uint32_t)(r * 128 + s * 16));
                const __half* src = gh + base + ((size_t)(tm + r) << 10) + k0 + s * 8;
                CP_ASYNC16(dst, src);
            }
#pragma unroll
            for (int q = 0; q < 8; q++) {
                int idx = tid + q * 128;
                int r = idx >> 4, s = idx & 15;
                uint32_t dst = sb + BOFF[buf] + (uint32_t)(r * B_PITCH + s * 16);
                const __half* src = gh + base + ((size_t)(k0 + r) << 10) + tn + s * 8;
                CP_ASYNC16(dst, src);
            }
            CP_COMMIT();
        };

        load_chunk(0, 0);
        for (int c = 0; c < 16; c++) {
            int buf = c & 1;
            if (c < 15) { load_chunk(c + 1, buf ^ 1); CP_WAIT1(); }
            else        { CP_WAIT0(); }
            __syncthreads();
            uint32_t abase = sb + AOFF[buf];
            uint32_t bbase = sb + BOFF[buf];
#pragma unroll
            for (int kk = 0; kk < 64; kk += 16) {
                uint32_t af[4][4], bf[4][4];
#pragma unroll
                for (int mt = 0; mt < 4; mt++) {
                    int m = rb0 + mt * 16 + lm * 8 + lr;
                    uint32_t addr = abase + SWZ128((uint32_t)(m * 128 + kk * 2 + lk * 16));
                    LDSM4(af[mt][0], af[mt][1], af[mt][2], af[mt][3], addr);
                }
#pragma unroll
                for (int nt2 = 0; nt2 < 4; nt2++) {
                    int krow = kk + lm * 8 + lr;
                    int n = cb0 + nt2 * 16 + lk * 8;
                    uint32_t addr = bbase + (uint32_t)(krow * B_PITCH + n * 2);
                    LDSM4T(bf[nt2][0], bf[nt2][1], bf[nt2][2], bf[nt2][3], addr);
                }
#pragma unroll
                for (int mt = 0; mt < 4; mt++)
#pragma unroll
                    for (int nt = 0; nt < 8; nt++)
                        mma_fp16(acc[mt][nt], af[mt], &bf[nt >> 1][(nt & 1) * 2]);
            }
            __syncthreads();
        }

        int e = eb >> 3, b_ = eb & 7;
        size_t obase = (size_t)(2 * e + 1) * (16ull << 20) + ((size_t)b_ << 10) * 2048;
#pragma unroll
        for (int mt = 0; mt < 4; mt++) {
#pragma unroll
            for (int half = 0; half < 2; half++) {
                int i = tm + rb0 + mt * 16 + gid + half * 8;
                size_t rowb = obase + (size_t)i * 2048;
#pragma unroll
                for (int nt = 0; nt < 8; nt++) {
                    int j = tn + cb0 + nt * 8 + tig * 2;
                    float2 v;
                    v.x = acc[mt][nt][half * 2 + 0];
                    v.y = acc[mt][nt][half * 2 + 1];
                    if (i == j) v.x = 0.f;
                    if (i == j + 1) v.y = 0.f;
                    *(float2*)&out[rowb + j] = v;
                    *(float2*)&out[rowb + 1024 + j] = v;
                }
            }
        }
    }
}

// ---------------------------------------------------------------------------
extern "C" void kernel_launch(void* const* d_in, const int* in_sizes, int n_in,
                              void* d_out, int out_size) {
    const float* hd   = (const float*)d_in[0];
    const float* embd = (const float*)d_in[1];
    const float* embu = (const float*)d_in[2];
    const float* adj0 = (const float*)d_in[3];
    const float* adj1 = (const float*)d_in[4];
    const float* W1   = (const float*)d_in[5];
    const float* b1   = (const float*)d_in[6];
    const float* gam  = (const float*)d_in[7];
    const float* bet  = (const float*)d_in[8];
    const float* W2   = (const float*)d_in[9];
    const float* b2   = (const float*)d_in[10];
    const float* WQ   = (const float*)d_in[11];
    const float* WK   = (const float*)d_in[12];
    float* out = (float*)d_out;

    float *ph, *ppart, *pQ, *pK;
    __half* pgh;
    cudaGetSymbolAddress((void**)&ph,    d_h);
    cudaGetSymbolAddress((void**)&ppart, d_part);
    cudaGetSymbolAddress((void**)&pQ,    d_Q);
    cudaGetSymbolAddress((void**)&pK,    d_K);
    cudaGetSymbolAddress((void**)&pgh,   d_gh);

    k_h<<<2048, 256>>>(hd, W1, b1, ph);
    k_stats1<<<64, 256>>>(ph, ppart);
    k_dyqk<<<512, 256>>>(ph, ppart, gam, bet, W2, b2, embd, embu, WQ, WK, pQ, pK);

    int attn_smem = (512 + 2 * SK_FLOATS + 16 * 1024 + 64) * (int)sizeof(float);
    cudaFuncSetAttribute(k_attn, cudaFuncAttributeMaxDynamicSharedMemorySize, attn_smem);
    k_attn<<<1024, 512, attn_smem>>>(pQ, pK, adj0, adj1, pgh, out);

    cudaFuncSetAttribute(k_gemm_fp16, cudaFuncAttributeMaxDynamicSharedMemorySize, GEMM_SMEM);
    k_gemm_fp16<<<296, 128, GEMM_SMEM>>>(pgh, out);
}

// round 15
// speedup vs baseline: 1.1190x; 1.1190x over previous
#include <cuda_runtime.h>
#include <cuda_fp16.h>
#include <cstdint>
#include <math.h>

// Problem constants
#define NB 8
#define LL 12
#define NN 1024
#define HH 32
#define H2 64
#define AF 48
#define NDIM 16

// Scratch (device globals)
__device__ float d_h[8192 * H2];
__device__ float d_part[64][H2][2];
__device__ float d_Q[2 * 8192 * HH];
__device__ float d_K[2 * 8192 * HH];
__device__ __half d_gh[16ull * 1024 * 1024];   // 32 MB fp16 graphs

extern __shared__ char dynsmem[];

// ---------------------------------------------------------------------------
#define SWZ128(o) ((o) ^ (((o) >> 3) & 0x70))
#define CP_ASYNC16(dst, src) asm volatile("cp.async.cg.shared.global [%0], [%1], 16;" :: "r"(dst), "l"(src))
#define CP_COMMIT() asm volatile("cp.async.commit_group;" ::: "memory")
#define CP_WAIT1() asm volatile("cp.async.wait_group 1;" ::: "memory")
#define CP_WAIT0() asm volatile("cp.async.wait_group 0;" ::: "memory")
#define LDSM4(r0, r1, r2, r3, addr) \
    asm volatile("ldmatrix.sync.aligned.m8n8.x4.shared.b16 {%0,%1,%2,%3}, [%4];" \
        : "=r"(r0), "=r"(r1), "=r"(r2), "=r"(r3) : "r"(addr))
#define LDSM4T(r0, r1, r2, r3, addr) \
    asm volatile("ldmatrix.sync.aligned.m8n8.x4.trans.shared.b16 {%0,%1,%2,%3}, [%4];" \
        : "=r"(r0), "=r"(r1), "=r"(r2), "=r"(r3) : "r"(addr))

__device__ __forceinline__ uint32_t smem_u32(const void* p) {
    uint32_t a;
    asm("{ .reg .u64 t; cvta.to.shared.u64 t, %1; cvt.u32.u64 %0, t; }" : "=r"(a) : "l"(p));
    return a;
}
__device__ __forceinline__ float ex2(float x) {
    float y;
    asm("ex2.approx.ftz.f32 %0, %1;" : "=f"(y) : "f"(x));
    return y;
}
__device__ __forceinline__ void mma_fp16(float* c, const uint32_t* a, const uint32_t* b) {
    asm volatile(
        "mma.sync.aligned.m16n8k16.row.col.f32.f16.f16.f32 "
        "{%0,%1,%2,%3}, {%4,%5,%6,%7}, {%8,%9}, {%0,%1,%2,%3};"
        : "+f"(c[0]), "+f"(c[1]), "+f"(c[2]), "+f"(c[3])
        : "r"(a[0]), "r"(a[1]), "r"(a[2]), "r"(a[3]), "r"(b[0]), "r"(b[1]));
}

// ---------------------------------------------------------------------------
// Kernel 1: h = relu(X @ W1 + b1)
__global__ void k_h(const float* __restrict__ hd, const float* __restrict__ W1,
                    const float* __restrict__ b1, float* __restrict__ h) {
    __shared__ float sW[LL * H2];
    __shared__ float sb[H2];
    int tid = threadIdx.x;
    for (int i = tid; i < LL * H2; i += 256) sW[i] = W1[i];
    if (tid < H2) sb[tid] = b1[tid];
    __syncthreads();
    int row = blockIdx.x * 4 + (tid >> 6);
    int col = tid & 63;
    int b = row >> 10, n = row & 1023;
    float acc = sb[col];
#pragma unroll
    for (int l = 0; l < LL; l++)
        acc += hd[((size_t)(b * LL + l) << 10) + n] * sW[l * H2 + col];
    h[(size_t)row * H2 + col] = fmaxf(acc, 0.f);
}

// ---------------------------------------------------------------------------
// Kernel 2: coalesced partial BN sums. 64 blocks x 128 rows each.
__global__ void k_stats1(const float* __restrict__ h, float* __restrict__ part) {
    __shared__ float ps[4][H2], ps2[4][H2];
    int tid = threadIdx.x;
    int c = tid & 63, r0 = tid >> 6;
    int p = blockIdx.x;
    float s = 0.f, s2 = 0.f;
#pragma unroll
    for (int i = 0; i < 32; i++) {
        float v = h[(size_t)(p * 128 + i * 4 + r0) * H2 + c];
        s += v; s2 += v * v;
    }
    ps[r0][c] = s; ps2[r0][c] = s2;
    __syncthreads();
    if (tid < H2) {
        float a = 0.f, b = 0.f;
#pragma unroll
        for (int j = 0; j < 4; j++) { a += ps[j][tid]; b += ps2[j][tid]; }
        part[(p * H2 + tid) * 2 + 0] = a;
        part[(p * H2 + tid) * 2 + 1] = b;
    }
}

// ---------------------------------------------------------------------------
// Kernel 3: fused BN-finalize + dy + Q/K projections.
// 16 rows per 256-thread block, 512 blocks.
__global__ void __launch_bounds__(256)
k_dyqk(const float* __restrict__ h, const float* __restrict__ part,
       const float* __restrict__ gamma, const float* __restrict__ beta,
       const float* __restrict__ W2, const float* __restrict__ b2,
       const float* __restrict__ embd, const float* __restrict__ embu,
       const float* __restrict__ WQ, const float* __restrict__ WK,
       float* __restrict__ Q, float* __restrict__ K) {
    __shared__ float sW2[H2 * HH];
    __shared__ float sWQ[AF * HH];
    __shared__ float sWK[AF * HH];
    __shared__ float sb2[HH];
    __shared__ float ssc[H2], ssh[H2];
    __shared__ float shh[16][H2];
    __shared__ float sed[16][NDIM], seu[16][NDIM];
    __shared__ float sdy[16][HH];
    int tid = threadIdx.x;
    int row0 = blockIdx.x * 16;
    int n0 = row0 & 1023;

    if (tid < H2) {
        float s = 0.f, s2 = 0.f;
#pragma unroll 8
        for (int p = 0; p < 64; p++) {
            s  += part[(p * H2 + tid) * 2 + 0];
            s2 += part[(p * H2 + tid) * 2 + 1];
        }
        float mu = s * (1.f / 8192.f);
        float var = s2 * (1.f / 8192.f) - mu * mu;
        float sc = gamma[tid] * rsqrtf(var + 1e-5f);
        ssc[tid] = sc;
        ssh[tid] = beta[tid] - mu * sc;
    }
    for (int i = tid; i < H2 * HH; i += 256) sW2[i] = W2[i];
    for (int i = tid; i < AF * HH; i += 256) { sWQ[i] = WQ[i]; sWK[i] = WK[i]; }
    if (tid < HH) sb2[tid] = b2[tid];
    if (tid < 16 * NDIM) {
        int r = tid >> 4, k = tid & 15;
        sed[r][k] = embd[(n0 + r) * NDIM + k];
        seu[r][k] = embu[(n0 + r) * NDIM + k];
    }
    __syncthreads();
    for (int i = tid; i < 16 * H2; i += 256) {
        int r = i >> 6, c = i & 63;
        shh[r][c] = h[(size_t)(row0 + r) * H2 + c] * ssc[c] + ssh[c];
    }
    __syncthreads();

    int rr = tid >> 5, c = tid & 31;
#pragma unroll
    for (int p = 0; p < 2; p++) {
        int r = p * 8 + rr;
        float acc = sb2[c];
#pragma unroll
        for (int k = 0; k < H2; k++) acc += shh[r][k] * sW2[k * HH + c];
        sdy[r][c] = acc;
    }
    __syncthreads();

#pragma unroll
    for (int p = 0; p < 2; p++) {
        int r = p * 8 + rr;
        float q0 = 0.f, k0 = 0.f;
#pragma unroll
        for (int k = 0; k < HH; k++) {
            float f = sdy[r][k];
            q0 += f * sWQ[k * HH + c];
            k0 += f * sWK[k * HH + c];
        }
        float qd = q0, qu = q0, kd = k0, ku = k0;
#pragma unroll
        for (int k = 0; k < NDIM; k++) {
            float wq = sWQ[(HH + k) * HH + c];
            float wk = sWK[(HH + k) * HH + c];
            qd += sed[r][k] * wq; qu += seu[r][k] * wq;
            kd += sed[r][k] * wk; ku += seu[r][k] * wk;
        }
        size_t od = (size_t)(row0 + r) * HH + c;
        size_t ou = (size_t)(8192 + row0 + r) * HH + c;
        Q[od] = qd; Q[ou] = qu;
        K[od] = kd; K[ou] = ku;
    }
}

// ---------------------------------------------------------------------------
// Kernel 4: attention (R13 structure). 16 rows / 512 threads per CTA; K staged
// via 16B cp.async double buffering (2 CP_ASYNC16/thread/chunk vs 8 CP_ASYNC4).
// Raw logits to sE; phase 2 fully float4-vectorized (exp+mask+sum+writes).
#define SK_P 36
#define SK_FLOATS (128 * SK_P)
#define PSC 0.25507600725815733f   // (1/sqrt(32)) * log2(e)
__global__ void __launch_bounds__(512, 2)
k_attn(const float* __restrict__ Q, const float* __restrict__ K,
       const float* __restrict__ adj0, const float* __restrict__ adj1,
       __half* __restrict__ gh, float* __restrict__ out) {
    float* smemf = (float*)dynsmem;
    float* sQ = smemf;                            // 512
    float* sK0 = smemf + 512;                     // 128*36
    float* sK1 = sK0 + SK_FLOATS;
    float* sE = sK1 + SK_FLOATS;                  // 16*1024
    uint32_t sk0a = smem_u32(sK0), sk1a = smem_u32(sK1);
    int tid = threadIdx.x;
    int blk = blockIdx.x;
    int e = blk >> 9;
    int rb = blk & 511;
    int b = rb >> 6;
    int row0 = (rb & 63) * 16;
    const float* adj = e ? adj1 : adj0;
    size_t qbase = ((size_t)e * 8192 + b * 1024 + row0) * HH;
    size_t kbase = ((size_t)e * 8192 + b * 1024) * HH;
    sQ[tid] = Q[qbase + tid];
    int tg = tid >> 7;        // 0..3 -> rows tg*4..tg*4+3
    int tl = tid & 127;       // column within chunk
    int r0 = tg * 4;

    // 16B staging: i4 = tid + p*512 (p<2); m = i4>>3, s = i4&7
    // dst word-off = m*SK_P + s*4 (16B aligned since SK_P*4 = 144 = 9*16)
    {
#pragma unroll
        for (int p = 0; p < 2; p++) {
            int i4 = tid + p * 512;
            int m = i4 >> 3, s = i4 & 7;
            CP_ASYNC16(sk0a + (uint32_t)(m * SK_P + s * 4) * 4, &K[kbase + i4 * 4]);
        }
        CP_COMMIT();
    }

    for (int t = 0; t < 8; t++) {
        __syncthreads();
        if (t < 7) {
            uint32_t dst = ((t + 1) & 1) ? sk1a : sk0a;
#pragma unroll
            for (int p = 0; p < 2; p++) {
                int i4 = tid + p * 512;
                int m = i4 >> 3, s = i4 & 7;
                CP_ASYNC16(dst + (uint32_t)(m * SK_P + s * 4) * 4,
                           &K[kbase + (t + 1) * 4096 + i4 * 4]);
            }
            CP_COMMIT();
            CP_WAIT1();
        } else {
            CP_WAIT0();
        }
        __syncthreads();
        float* sK = (t & 1) ? sK1 : sK0;
        float4 kreg[8];
#pragma unroll
        for (int k4 = 0; k4 < 8; k4++)
            kreg[k4] = *(const float4*)&sK[tl * SK_P + k4 * 4];
#pragma unroll
        for (int r = 0; r < 4; r++) {
            float acc = 0.f;
#pragma unroll
            for (int q4 = 0; q4 < 8; q4++) {
                float4 qv = *(const float4*)&sQ[(r0 + r) * 32 + q4 * 4];
                acc += qv.x * kreg[q4].x;
                acc += qv.y * kreg[q4].y;
                acc += qv.z * kreg[q4].z;
                acc += qv.w * kreg[q4].w;
            }
            sE[(r0 + r) * 1024 + t * 128 + tl] = acc * PSC;
        }
    }
    __syncthreads();

    // phase 2: per-warp row, float4 lanes
    int w = tid >> 5, lane = tid & 31;   // w = 0..15 -> row
    int n = row0 + w;
    float4 v[8];
    float sum = 0.f;
#pragma unroll
    for (int i = 0; i < 8; i++) {
        int m0 = i * 128 + lane * 4;
        float4 le = *(const float4*)&sE[w * 1024 + m0];
        float4 a = *(const float4*)&adj[(size_t)n * 1024 + m0];
        float4 t;
        t.x = ex2(le.x) * (a.x + 1e-7f);
        t.y = ex2(le.y) * (a.y + 1e-7f);
        t.z = ex2(le.z) * (a.z + 1e-7f);
        t.w = ex2(le.w) * (a.w + 1e-7f);
        v[i] = t;
        sum += t.x + t.y + t.z + t.w;
    }
    for (int o = 16; o > 0; o >>= 1) sum += __shfl_xor_sync(0xffffffffu, sum, o);
    float inv = 1.f / sum;
    if (!isfinite(inv)) inv = 0.f;

    size_t gbase = ((size_t)e * 8192 + b * 1024 + n) * 1024;
    size_t obase = (size_t)(2 * e) * (16ull << 20) + ((size_t)b * 1024 + n) * 2048;
#pragma unroll
    for (int i = 0; i < 8; i++) {
        int m0 = i * 128 + lane * 4;
        float4 val;
        val.x = v[i].x * inv; val.y = v[i].y * inv;
        val.z = v[i].z * inv; val.w = v[i].w * inv;
        __half2 lo = __floats2half2_rn(val.x, val.y);
        __half2 hi = __floats2half2_rn(val.z, val.w);
        uint2 gv = make_uint2(*(uint32_t*)&lo, *(uint32_t*)&hi);
        *(uint2*)&gh[gbase + m0] = gv;
        int d = n - m0;
        if (d >= 0 && d < 4) ((float*)&val)[d] = 0.f;
        *(float4*)&out[obase + m0] = val;
        *(float4*)&out[obase + 1024 + m0] = val;
    }
}

// ---------------------------------------------------------------------------
// Kernel 5: fp16 mma.sync GEMM, persistent CTAs. Block tile 128x128, 128 thr,
// warp tile 64x64, k-chunk 64, cp.async double buffering, 2 CTAs/SM, grid=296.
#define A_BYTES 16384
#define B_PITCH 272
#define B_BYTES (64 * B_PITCH)
#define GEMM_SMEM (2 * A_BYTES + 2 * B_BYTES)
#define N_TILES 1024

__global__ void __launch_bounds__(128, 2)
k_gemm_fp16(const __half* __restrict__ gh, float* __restrict__ out) {
    char* smem = dynsmem;
    uint32_t sb = smem_u32(smem);
    const uint32_t AOFF[2] = {0u, A_BYTES};
    const uint32_t BOFF[2] = {2 * A_BYTES, 2 * A_BYTES + B_BYTES};
    int tid = threadIdx.x;

    int wid = tid >> 5, lane = tid & 31;
    int gid = lane >> 2, tig = lane & 3;
    int warp_m = wid & 1, warp_n = wid >> 1;
    int rb0 = warp_m * 64, cb0 = warp_n * 64;
    int lr = lane & 7;
    int lm = (lane >> 3) & 1;
    int lk = lane >> 4;

    for (int tile = blockIdx.x; tile < N_TILES; tile += gridDim.x) {
        int eb = tile >> 6;
        int t6 = tile & 63;
        int tm = (t6 >> 3) * 128, tn = (t6 & 7) * 128;
        size_t base = (size_t)eb << 20;

        float acc[4][8][4];
#pragma unroll
        for (int i = 0; i < 4; i++)
#pragma unroll
            for (int j = 0; j < 8; j++)
#pragma unroll
                for (int q = 0; q < 4; q++) acc[i][j][q] = 0.f;

        auto load_chunk = [&](int c, int buf) {
            int k0 = c * 64;
#pragma unroll
            for (int q = 0; q < 8; q++) {
                int idx = tid + q * 128;
                int r = idx >> 3, s = idx & 7;
                uint32_t dst = sb + AOFF[buf] + SWZ128((uint32_t)(r * 128 + s * 16));
                const __half* src = gh + base + ((size_t)(tm + r) << 10) + k0 + s * 8;
                CP_ASYNC16(dst, src);
            }
#pragma unroll
            for (int q = 0; q < 8; q++) {
                int idx = tid + q * 128;
                int r = idx >> 4, s = idx & 15;
                uint32_t dst = sb + BOFF[buf] + (uint32_t)(r * B_PITCH + s * 16);
                const __half* src = gh + base + ((size_t)(k0 + r) << 10) + tn + s * 8;
                CP_ASYNC16(dst, src);
            }
            CP_COMMIT();
        };

        load_chunk(0, 0);
        for (int c = 0; c < 16; c++) {
            int buf = c & 1;
            if (c < 15) { load_chunk(c + 1, buf ^ 1); CP_WAIT1(); }
            else        { CP_WAIT0(); }
            __syncthreads();
            uint32_t abase = sb + AOFF[buf];
            uint32_t bbase = sb + BOFF[buf];
#pragma unroll
            for (int kk = 0; kk < 64; kk += 16) {
                uint32_t af[4][4], bf[4][4];
#pragma unroll
                for (int mt = 0; mt < 4; mt++) {
                    int m = rb0 + mt * 16 + lm * 8 + lr;
                    uint32_t addr = abase + SWZ128((uint32_t)(m * 128 + kk * 2 + lk * 16));
                    LDSM4(af[mt][0], af[mt][1], af[mt][2], af[mt][3], addr);
                }
#pragma unroll
                for (int nt2 = 0; nt2 < 4; nt2++) {
                    int krow = kk + lm * 8 + lr;
                    int n = cb0 + nt2 * 16 + lk * 8;
                    uint32_t addr = bbase + (uint32_t)(krow * B_PITCH + n * 2);
                    LDSM4T(bf[nt2][0], bf[nt2][1], bf[nt2][2], bf[nt2][3], addr);
                }
#pragma unroll
                for (int mt = 0; mt < 4; mt++)
#pragma unroll
                    for (int nt = 0; nt < 8; nt++)
                        mma_fp16(acc[mt][nt], af[mt], &bf[nt >> 1][(nt & 1) * 2]);
            }
            __syncthreads();
        }

        int e = eb >> 3, b_ = eb & 7;
        size_t obase = (size_t)(2 * e + 1) * (16ull << 20) + ((size_t)b_ << 10) * 2048;
#pragma unroll
        for (int mt = 0; mt < 4; mt++) {
#pragma unroll
            for (int half = 0; half < 2; half++) {
                int i = tm + rb0 + mt * 16 + gid + half * 8;
                size_t rowb = obase + (size_t)i * 2048;
#pragma unroll
                for (int nt = 0; nt < 8; nt++) {
                    int j = tn + cb0 + nt * 8 + tig * 2;
                    float2 v;
                    v.x = acc[mt][nt][half * 2 + 0];
                    v.y = acc[mt][nt][half * 2 + 1];
                    if (i == j) v.x = 0.f;
                    if (i == j + 1) v.y = 0.f;
                    *(float2*)&out[rowb + j] = v;
                    *(float2*)&out[rowb + 1024 + j] = v;
                }
            }
        }
    }
}

// ---------------------------------------------------------------------------
extern "C" void kernel_launch(void* const* d_in, const int* in_sizes, int n_in,
                              void* d_out, int out_size) {
    const float* hd   = (const float*)d_in[0];
    const float* embd = (const float*)d_in[1];
    const float* embu = (const float*)d_in[2];
    const float* adj0 = (const float*)d_in[3];
    const float* adj1 = (const float*)d_in[4];
    const float* W1   = (const float*)d_in[5];
    const float* b1   = (const float*)d_in[6];
    const float* gam  = (const float*)d_in[7];
    const float* bet  = (const float*)d_in[8];
    const float* W2   = (const float*)d_in[9];
    const float* b2   = (const float*)d_in[10];
    const float* WQ   = (const float*)d_in[11];
    const float* WK   = (const float*)d_in[12];
    float* out = (float*)d_out;

    float *ph, *ppart, *pQ, *pK;
    __half* pgh;
    cudaGetSymbolAddress((void**)&ph,    d_h);
    cudaGetSymbolAddress((void**)&ppart, d_part);
    cudaGetSymbolAddress((void**)&pQ,    d_Q);
    cudaGetSymbolAddress((void**)&pK,    d_K);
    cudaGetSymbolAddress((void**)&pgh,   d_gh);

    k_h<<<2048, 256>>>(hd, W1, b1, ph);
    k_stats1<<<64, 256>>>(ph, ppart);
    k_dyqk<<<512, 256>>>(ph, ppart, gam, bet, W2, b2, embd, embu, WQ, WK, pQ, pK);

    int attn_smem = (512 + 2 * SK_FLOATS + 16 * 1024) * (int)sizeof(float);
    cudaFuncSetAttribute(k_attn, cudaFuncAttributeMaxDynamicSharedMemorySize, attn_smem);
    k_attn<<<1024, 512, attn_smem>>>(pQ, pK, adj0, adj1, pgh, out);

    cudaFuncSetAttribute(k_gemm_fp16, cudaFuncAttributeMaxDynamicSharedMemorySize, GEMM_SMEM);
    k_gemm_fp16<<<296, 128, GEMM_SMEM>>>(pgh, out);
}